// round 1
// baseline (speedup 1.0000x reference)
#include <cuda_runtime.h>
#include <math.h>

#define NN 100000
#define GG 6000
#define EE 400000
#define HH 128

// ---------------- scratch (device globals; no runtime allocation) ----------------
__device__ float g_q[(size_t)NN * HH];      // q = node_emb @ Wq + bq
__device__ float g_k[(size_t)GG * HH];      // k = group_emb @ Wk + bk
__device__ float g_val[(size_t)GG * HH];    // val = group_emb @ Wval + bval
__device__ float g_ms[(size_t)EE * HH];     // per-edge m_s
__device__ float g_msn[(size_t)NN * HH];    // scatter-added m_s per node
__device__ float g_A[(size_t)NN * HH];      // m_s_node @ L0
__device__ float g_B[(size_t)NN * HH];      // m_s_node @ L4
__device__ float g_C[(size_t)NN * HH];      // m_s_node @ L5

__device__ __forceinline__ void red_v4(float* addr, float4 v) {
    asm volatile("red.global.add.v4.f32 [%0], {%1,%2,%3,%4};"
                 :: "l"(addr), "f"(v.x), "f"(v.y), "f"(v.z), "f"(v.w) : "memory");
}

__device__ __forceinline__ float silu_f(float x) {
    return x / (1.0f + expf(-x));
}

// ---------------- generic [R,128] @ [128,128] + bias GEMM ----------------
// CTA: 64 rows x 128 cols, 256 threads. smem: W(64KB) + X tile(32KB) = 96KB.
__global__ void gemm128_bias(const float* __restrict__ X, const float* __restrict__ W,
                             const float* __restrict__ bias, float* __restrict__ Y, int R)
{
    extern __shared__ float sm[];
    float* Ws = sm;            // 128*128
    float* Xs = sm + 128 * 128; // 64*128
    const int t = threadIdx.x;
    const int r0 = blockIdx.x * 64;

    // load W (4096 float4)
    #pragma unroll
    for (int i = 0; i < 16; i++) {
        int idx = t + i * 256;
        ((float4*)Ws)[idx] = ((const float4*)W)[idx];
    }
    // load X tile (2048 float4), guard rows
    #pragma unroll
    for (int i = 0; i < 8; i++) {
        int idx = t + i * 256;       // float4 index within tile
        int row = idx >> 5;          // 32 float4 per row
        float4 v = make_float4(0.f, 0.f, 0.f, 0.f);
        if (r0 + row < R) v = ((const float4*)X)[(size_t)(r0 + row) * 32 + (idx & 31)];
        ((float4*)Xs)[idx] = v;
    }
    __syncthreads();

    const int tx = t & 31, ty = t >> 5;
    const int c4 = tx * 4;
    float acc[8][4];
    #pragma unroll
    for (int r = 0; r < 8; r++)
        #pragma unroll
        for (int c = 0; c < 4; c++) acc[r][c] = 0.f;

    #pragma unroll 4
    for (int k = 0; k < 128; k++) {
        float4 w = *(float4*)&Ws[k * 128 + c4];
        #pragma unroll
        for (int r = 0; r < 8; r++) {
            float x = Xs[(ty * 8 + r) * 128 + k];
            acc[r][0] += x * w.x; acc[r][1] += x * w.y;
            acc[r][2] += x * w.z; acc[r][3] += x * w.w;
        }
    }

    float4 b4 = make_float4(0.f, 0.f, 0.f, 0.f);
    if (bias) b4 = *(const float4*)&bias[c4];
    #pragma unroll
    for (int r = 0; r < 8; r++) {
        int row = r0 + ty * 8 + r;
        if (row < R) {
            float4 o = make_float4(acc[r][0] + b4.x, acc[r][1] + b4.y,
                                   acc[r][2] + b4.z, acc[r][3] + b4.w);
            *(float4*)&Y[(size_t)row * 128 + c4] = o;
        }
    }
}

// ---------------- per-edge attention + m_s + m_s_node scatter ----------------
// one warp per edge; lane l owns 4 channels (head = l>>2).
__global__ void edge_attn_kernel(const int* __restrict__ node_idx,
                                 const int* __restrict__ group_idx,
                                 const float* __restrict__ edge_attr)
{
    int e = (blockIdx.x * blockDim.x + threadIdx.x) >> 5;
    if (e >= EE) return;
    int lane = threadIdx.x & 31;
    int n = node_idx[e], g = group_idx[e];
    int j4 = lane * 4;

    float4 q4 = *(const float4*)&g_q[(size_t)n * 128 + j4];
    float4 k4 = *(const float4*)&g_k[(size_t)g * 128 + j4];
    float4 a4 = *(const float4*)&edge_attr[(size_t)e * 128 + j4];

    float s = q4.x * k4.x * a4.x + q4.y * k4.y * a4.y
            + q4.z * k4.z * a4.z + q4.w * k4.w * a4.w;
    // reduce within 4-lane head group
    s += __shfl_xor_sync(0xffffffffu, s, 1);
    s += __shfl_xor_sync(0xffffffffu, s, 2);
    s *= 0.25f;                 // 1/sqrt(16)
    float attn = silu_f(s);

    float4 v4 = *(const float4*)&g_val[(size_t)g * 128 + j4];
    float4 m = make_float4(v4.x * attn, v4.y * attn, v4.z * attn, v4.w * attn);
    *(float4*)&g_ms[(size_t)e * 128 + j4] = m;
    red_v4(&g_msn[(size_t)n * 128 + j4], m);
}

// ---------------- fused edge MLPs + m_v scatter (persistent) ----------------
// smem: 4 MLP weights (131KB) + biases + tiles; 32 edges per tile; 256 threads.
#define MLP_SMEM_FLOATS 49696
__global__ void edge_mlp_kernel(const int* __restrict__ node_idx,
                                const int* __restrict__ group_idx,
                                const float* __restrict__ edge_vec,
                                const float* __restrict__ group_vec,
                                const float* __restrict__ Wp1, const float* __restrict__ bp1,
                                const float* __restrict__ Wp2, const float* __restrict__ bp2,
                                const float* __restrict__ Ws1, const float* __restrict__ bs1,
                                const float* __restrict__ Ws2, const float* __restrict__ bs2,
                                float* __restrict__ dv_out)
{
    extern __shared__ float sm[];
    float* Wp1s = sm;              // 8192   [128][64]
    float* Wp2s = sm + 8192;       // 8192   [64][128]
    float* Ws1s = sm + 16384;      // 8192
    float* Ws2s = sm + 24576;      // 8192
    float* bp1s = sm + 32768;      // 64
    float* bp2s = sm + 32832;      // 128
    float* bs1s = sm + 32960;      // 64
    float* bs2s = sm + 33024;      // 128
    float* msS  = sm + 33152;      // 32*128
    float* hpS  = sm + 37248;      // 32*64
    float* hsS  = sm + 39296;      // 32*64
    float* spS  = sm + 41344;      // 32*128
    float* svS  = sm + 45440;      // 32*128
    float* uS   = sm + 49536;      // 32*3
    int*   nS   = (int*)(sm + 49632); // 32
    int*   gS   = (int*)(sm + 49664); // 32

    const int t = threadIdx.x;

    // load weights once per CTA
    {
        const float* srcs[4] = { Wp1, Wp2, Ws1, Ws2 };
        float* dsts[4] = { Wp1s, Wp2s, Ws1s, Ws2s };
        #pragma unroll
        for (int a = 0; a < 4; a++) {
            #pragma unroll
            for (int i = 0; i < 8; i++) {
                int idx = t + i * 256;   // 2048 float4
                ((float4*)dsts[a])[idx] = ((const float4*)srcs[a])[idx];
            }
        }
        if (t < 64)  bp1s[t] = bp1[t];
        if (t < 128) bp2s[t] = bp2[t];
        if (t < 64)  bs1s[t] = bs1[t];
        if (t < 128) bs2s[t] = bs2[t];
    }

    const int nTiles = (EE + 31) / 32;
    for (int tile = blockIdx.x; tile < nTiles; tile += gridDim.x) {
        const int e0 = tile * 32;
        __syncthreads();   // prior tile consumers done before overwriting smem

        // load m_s tile (1024 float4) + per-edge scalars
        #pragma unroll
        for (int i = 0; i < 4; i++) {
            int idx = t + i * 256;
            int e = e0 + (idx >> 5);
            float4 v = make_float4(0.f, 0.f, 0.f, 0.f);
            if (e < EE) v = ((const float4*)g_ms)[(size_t)e0 * 32 + idx];
            ((float4*)msS)[idx] = v;
        }
        if (t < 32) {
            int e = e0 + t;
            nS[t] = (e < EE) ? node_idx[e] : 0;
            gS[t] = (e < EE) ? group_idx[e] : 0;
        }
        if (t < 96) {
            int e = e0 + t / 3;
            uS[t] = (e < EE) ? -edge_vec[(size_t)e0 * 3 + t] : 0.f;
        }
        __syncthreads();

        // layer 1 (both MLPs): thread owns 2 rows x 4 hidden cols
        {
            const int jg = t & 15;  const int j4 = jg * 4;
            const int rg = t >> 4;  // rows rg*2, rg*2+1
            float4 ap[2], as_[2];
            ap[0] = ap[1] = as_[0] = as_[1] = make_float4(0.f, 0.f, 0.f, 0.f);
            #pragma unroll 4
            for (int k = 0; k < 128; k++) {
                float4 wp = *(float4*)&Wp1s[k * 64 + j4];
                float4 ws = *(float4*)&Ws1s[k * 64 + j4];
                #pragma unroll
                for (int r = 0; r < 2; r++) {
                    float x = msS[(rg * 2 + r) * 128 + k];
                    ap[r].x += x * wp.x; ap[r].y += x * wp.y; ap[r].z += x * wp.z; ap[r].w += x * wp.w;
                    as_[r].x += x * ws.x; as_[r].y += x * ws.y; as_[r].z += x * ws.z; as_[r].w += x * ws.w;
                }
            }
            float4 b1p = *(float4*)&bp1s[j4];
            float4 b1s = *(float4*)&bs1s[j4];
            #pragma unroll
            for (int r = 0; r < 2; r++) {
                int row = rg * 2 + r;
                float4 hp = make_float4(silu_f(ap[r].x + b1p.x), silu_f(ap[r].y + b1p.y),
                                        silu_f(ap[r].z + b1p.z), silu_f(ap[r].w + b1p.w));
                float4 hs = make_float4(silu_f(as_[r].x + b1s.x), silu_f(as_[r].y + b1s.y),
                                        silu_f(as_[r].z + b1s.z), silu_f(as_[r].w + b1s.w));
                *(float4*)&hpS[row * 64 + j4] = hp;
                *(float4*)&hsS[row * 64 + j4] = hs;
            }
        }
        __syncthreads();

        // layer 2: thread owns 4 rows x 4 out cols
        {
            const int tx = t & 31; const int c4 = tx * 4;
            const int ty = t >> 5;  // rows ty*4 .. +3
            float4 accp[4], accs[4];
            #pragma unroll
            for (int r = 0; r < 4; r++) { accp[r] = make_float4(0.f,0.f,0.f,0.f); accs[r] = make_float4(0.f,0.f,0.f,0.f); }
            #pragma unroll 4
            for (int k = 0; k < 64; k++) {
                float4 wp = *(float4*)&Wp2s[k * 128 + c4];
                float4 ws = *(float4*)&Ws2s[k * 128 + c4];
                #pragma unroll
                for (int r = 0; r < 4; r++) {
                    int row = ty * 4 + r;
                    float hp = hpS[row * 64 + k];
                    float hs = hsS[row * 64 + k];
                    accp[r].x += hp * wp.x; accp[r].y += hp * wp.y; accp[r].z += hp * wp.z; accp[r].w += hp * wp.w;
                    accs[r].x += hs * ws.x; accs[r].y += hs * ws.y; accs[r].z += hs * ws.z; accs[r].w += hs * ws.w;
                }
            }
            float4 b2p = *(float4*)&bp2s[c4];
            float4 b2s = *(float4*)&bs2s[c4];
            #pragma unroll
            for (int r = 0; r < 4; r++) {
                int row = ty * 4 + r;
                float4 sp = make_float4(accp[r].x + b2p.x, accp[r].y + b2p.y, accp[r].z + b2p.z, accp[r].w + b2p.w);
                float4 sv = make_float4(accs[r].x + b2s.x, accs[r].y + b2s.y, accs[r].z + b2s.z, accs[r].w + b2s.w);
                *(float4*)&spS[row * 128 + c4] = sp;
                *(float4*)&svS[row * 128 + c4] = sv;
            }
        }
        __syncthreads();

        // m_v = sp*u + sv*group_vec[g]; scatter into dv_out. 3072 float4 units.
        #pragma unroll
        for (int i = 0; i < 12; i++) {
            int flat = t + i * 256;
            int r = flat / 96;
            int rem = flat - r * 96;
            int d = rem >> 5;
            int c = rem & 31;
            int e = e0 + r;
            if (e < EE) {
                float4 sp = *(float4*)&spS[r * 128 + c * 4];
                float4 sv = *(float4*)&svS[r * 128 + c * 4];
                float u = uS[r * 3 + d];
                int g = gS[r];
                int n = nS[r];
                float4 gv = *(const float4*)&group_vec[((size_t)g * 3 + d) * 128 + c * 4];
                float4 mv = make_float4(sp.x * u + sv.x * gv.x, sp.y * u + sv.y * gv.y,
                                        sp.z * u + sv.z * gv.z, sp.w * u + sv.w * gv.w);
                red_v4(&dv_out[((size_t)n * 3 + d) * 128 + c * 4], mv);
            }
        }
    }
}

// ---------------- dx: (sum_d (nv@L2)*(nv@L3)) * B + C  (persistent) ----------------
__global__ void dx_kernel(const float* __restrict__ node_vec,
                          const float* __restrict__ L2w, const float* __restrict__ L3w,
                          float* __restrict__ dx_out)
{
    extern __shared__ float sm[];
    float* L2s = sm;            // 16384
    float* L3s = sm + 16384;    // 16384
    float* nvS = sm + 32768;    // 32*3*128 = 12288
    const int t = threadIdx.x;

    #pragma unroll
    for (int i = 0; i < 16; i++) {
        int idx = t + i * 256;
        ((float4*)L2s)[idx] = ((const float4*)L2w)[idx];
        ((float4*)L3s)[idx] = ((const float4*)L3w)[idx];
    }

    const int nTiles = (NN + 31) / 32;
    for (int tile = blockIdx.x; tile < nTiles; tile += gridDim.x) {
        __syncthreads();
        #pragma unroll
        for (int i = 0; i < 12; i++) {
            int idx = t + i * 256;          // float4 idx within tile (3072)
            int n = tile * 32 + idx / 96;   // 96 float4 per node
            float4 v = make_float4(0.f,0.f,0.f,0.f);
            if (n < NN) v = ((const float4*)node_vec)[(size_t)tile * 3072 + idx];
            ((float4*)nvS)[idx] = v;
        }
        __syncthreads();

        const int tx = t & 31; const int c4 = tx * 4;
        const int ty = t >> 5;   // rows ty*4..+3
        float4 s4[4];
        #pragma unroll
        for (int r = 0; r < 4; r++) s4[r] = make_float4(0.f,0.f,0.f,0.f);

        #pragma unroll
        for (int d = 0; d < 3; d++) {
            float4 a[4], b[4];
            #pragma unroll
            for (int r = 0; r < 4; r++) { a[r] = make_float4(0.f,0.f,0.f,0.f); b[r] = make_float4(0.f,0.f,0.f,0.f); }
            #pragma unroll 4
            for (int k = 0; k < 128; k++) {
                float4 w2 = *(float4*)&L2s[k * 128 + c4];
                float4 w3 = *(float4*)&L3s[k * 128 + c4];
                #pragma unroll
                for (int r = 0; r < 4; r++) {
                    float x = nvS[((ty * 4 + r) * 3 + d) * 128 + k];
                    a[r].x += x * w2.x; a[r].y += x * w2.y; a[r].z += x * w2.z; a[r].w += x * w2.w;
                    b[r].x += x * w3.x; b[r].y += x * w3.y; b[r].z += x * w3.z; b[r].w += x * w3.w;
                }
            }
            #pragma unroll
            for (int r = 0; r < 4; r++) {
                s4[r].x += a[r].x * b[r].x; s4[r].y += a[r].y * b[r].y;
                s4[r].z += a[r].z * b[r].z; s4[r].w += a[r].w * b[r].w;
            }
        }
        #pragma unroll
        for (int r = 0; r < 4; r++) {
            int n = tile * 32 + ty * 4 + r;
            if (n < NN) {
                float4 B4 = *(const float4*)&g_B[(size_t)n * 128 + c4];
                float4 C4 = *(const float4*)&g_C[(size_t)n * 128 + c4];
                float4 o = make_float4(s4[r].x * B4.x + C4.x, s4[r].y * B4.y + C4.y,
                                       s4[r].z * B4.z + C4.z, s4[r].w * B4.w + C4.w);
                *(float4*)&dx_out[(size_t)n * 128 + c4] = o;
            }
        }
    }
}

// ---------------- dv: += A * (nv @ L1)  (persistent, RMW on dv_out) ----------------
__global__ void dv_kernel(const float* __restrict__ node_vec,
                          const float* __restrict__ L1w,
                          float* __restrict__ dv_out)
{
    extern __shared__ float sm[];
    float* L1s = sm;            // 16384
    float* nvS = sm + 16384;    // 12288
    const int t = threadIdx.x;

    #pragma unroll
    for (int i = 0; i < 16; i++) {
        int idx = t + i * 256;
        ((float4*)L1s)[idx] = ((const float4*)L1w)[idx];
    }

    const int nTiles = (NN + 31) / 32;
    for (int tile = blockIdx.x; tile < nTiles; tile += gridDim.x) {
        __syncthreads();
        #pragma unroll
        for (int i = 0; i < 12; i++) {
            int idx = t + i * 256;
            int n = tile * 32 + idx / 96;
            float4 v = make_float4(0.f,0.f,0.f,0.f);
            if (n < NN) v = ((const float4*)node_vec)[(size_t)tile * 3072 + idx];
            ((float4*)nvS)[idx] = v;
        }
        __syncthreads();

        const int tx = t & 31; const int c4 = tx * 4;
        const int ty = t >> 5;
        #pragma unroll
        for (int d = 0; d < 3; d++) {
            float4 acc[4];
            #pragma unroll
            for (int r = 0; r < 4; r++) acc[r] = make_float4(0.f,0.f,0.f,0.f);
            #pragma unroll 4
            for (int k = 0; k < 128; k++) {
                float4 w = *(float4*)&L1s[k * 128 + c4];
                #pragma unroll
                for (int r = 0; r < 4; r++) {
                    float x = nvS[((ty * 4 + r) * 3 + d) * 128 + k];
                    acc[r].x += x * w.x; acc[r].y += x * w.y; acc[r].z += x * w.z; acc[r].w += x * w.w;
                }
            }
            #pragma unroll
            for (int r = 0; r < 4; r++) {
                int n = tile * 32 + ty * 4 + r;
                if (n < NN) {
                    size_t o = ((size_t)n * 3 + d) * 128 + c4;
                    float4 mv = *(float4*)&dv_out[o];
                    float4 A4 = *(const float4*)&g_A[(size_t)n * 128 + c4];
                    mv.x += A4.x * acc[r].x; mv.y += A4.y * acc[r].y;
                    mv.z += A4.z * acc[r].z; mv.w += A4.w * acc[r].w;
                    *(float4*)&dv_out[o] = mv;
                }
            }
        }
    }
}

// ---------------- launch ----------------
extern "C" void kernel_launch(void* const* d_in, const int* in_sizes, int n_in,
                              void* d_out, int out_size)
{
    const int*   node_idx        = (const int*)d_in[0];
    const int*   group_idx       = (const int*)d_in[1];
    const float* node_embedding  = (const float*)d_in[2];
    const float* node_vec        = (const float*)d_in[3];
    const float* group_embedding = (const float*)d_in[4];
    const float* group_vec       = (const float*)d_in[5];
    const float* edge_attr       = (const float*)d_in[6];
    /* d_in[7] = edge_weight (unused by reference) */
    const float* edge_vec        = (const float*)d_in[8];
    const float* Wq  = (const float*)d_in[9];  const float* bq  = (const float*)d_in[10];
    const float* Wk  = (const float*)d_in[11]; const float* bk  = (const float*)d_in[12];
    const float* Wvl = (const float*)d_in[13]; const float* bvl = (const float*)d_in[14];
    const float* Wp1 = (const float*)d_in[15]; const float* bp1 = (const float*)d_in[16];
    const float* Wp2 = (const float*)d_in[17]; const float* bp2 = (const float*)d_in[18];
    const float* Ws1 = (const float*)d_in[19]; const float* bs1 = (const float*)d_in[20];
    const float* Ws2 = (const float*)d_in[21]; const float* bs2 = (const float*)d_in[22];
    const float* L0  = (const float*)d_in[23];
    const float* L1  = (const float*)d_in[24];
    const float* L2  = (const float*)d_in[25];
    const float* L3  = (const float*)d_in[26];
    const float* L4  = (const float*)d_in[27];
    const float* L5  = (const float*)d_in[28];

    float* dx = (float*)d_out;                       // [N,128]
    float* dv = (float*)d_out + (size_t)NN * HH;     // [N,3,128]

    // smem opt-ins (idempotent; legal during capture — not stream ops)
    cudaFuncSetAttribute(gemm128_bias,   cudaFuncAttributeMaxDynamicSharedMemorySize, 98304);
    cudaFuncSetAttribute(edge_mlp_kernel,cudaFuncAttributeMaxDynamicSharedMemorySize, MLP_SMEM_FLOATS * 4);
    cudaFuncSetAttribute(dx_kernel,      cudaFuncAttributeMaxDynamicSharedMemorySize, 180224);
    cudaFuncSetAttribute(dv_kernel,      cudaFuncAttributeMaxDynamicSharedMemorySize, 114688);

    float *p_q, *p_k, *p_val, *p_msn, *p_A, *p_B, *p_C;
    cudaGetSymbolAddress((void**)&p_q,   g_q);
    cudaGetSymbolAddress((void**)&p_k,   g_k);
    cudaGetSymbolAddress((void**)&p_val, g_val);
    cudaGetSymbolAddress((void**)&p_msn, g_msn);
    cudaGetSymbolAddress((void**)&p_A,   g_A);
    cudaGetSymbolAddress((void**)&p_B,   g_B);
    cudaGetSymbolAddress((void**)&p_C,   g_C);

    cudaMemsetAsync(p_msn, 0, sizeof(float) * (size_t)NN * HH, 0);
    cudaMemsetAsync(dv,    0, sizeof(float) * (size_t)NN * 3 * HH, 0);

    gemm128_bias<<<(NN + 63) / 64, 256, 98304>>>(node_embedding,  Wq,  bq,  p_q,   NN);
    gemm128_bias<<<(GG + 63) / 64, 256, 98304>>>(group_embedding, Wk,  bk,  p_k,   GG);
    gemm128_bias<<<(GG + 63) / 64, 256, 98304>>>(group_embedding, Wvl, bvl, p_val, GG);

    edge_attn_kernel<<<(EE * 32) / 256, 256>>>(node_idx, group_idx, edge_attr);

    edge_mlp_kernel<<<148, 256, MLP_SMEM_FLOATS * 4>>>(node_idx, group_idx, edge_vec, group_vec,
                                                       Wp1, bp1, Wp2, bp2, Ws1, bs1, Ws2, bs2, dv);

    gemm128_bias<<<(NN + 63) / 64, 256, 98304>>>(p_msn, L0, nullptr, p_A, NN);
    gemm128_bias<<<(NN + 63) / 64, 256, 98304>>>(p_msn, L4, nullptr, p_B, NN);
    gemm128_bias<<<(NN + 63) / 64, 256, 98304>>>(p_msn, L5, nullptr, p_C, NN);

    dx_kernel<<<148, 256, 180224>>>(node_vec, L2, L3, dx);
    dv_kernel<<<296, 256, 114688>>>(node_vec, L1, dv);
}